// round 1
// baseline (speedup 1.0000x reference)
#include <cuda_runtime.h>
#include <math.h>

// Problem constants
#define NB    4       // batch
#define SEQ   2048    // sequence
#define HID   1024    // hidden
#define NFREQ 513     // rfft freqs = HID/2 + 1
#define KPAD  1032    // 513 cos + 3 pad + 513 sin + 3 pad (float4/BK=8 friendly)
#define SINOFF 516    // sin base offset within a feature row
#define NROWS (NB*SEQ) // 8192 rows per tensor

// Scratch: phase feature matrices [NROWS, KPAD] for Q and K
__device__ float g_Fq[(size_t)NROWS * KPAD];
__device__ float g_Fk[(size_t)NROWS * KPAD];
// FFT twiddles W_1024^k = exp(-2*pi*i*k/1024), k = 0..511
__device__ float g_twr[512];
__device__ float g_twi[512];

// ---------------------------------------------------------------------------
// Twiddle init (double precision for accuracy); cheap, re-run every launch.
// ---------------------------------------------------------------------------
__global__ void init_twiddles_kernel() {
    int t = threadIdx.x;
    if (t < 512) {
        double ang = -2.0 * 3.141592653589793238462643 * (double)t / 1024.0;
        g_twr[t] = (float)cos(ang);
        g_twi[t] = (float)sin(ang);
    }
}

// ---------------------------------------------------------------------------
// Per-row 1024-pt radix-2 FFT (real input) -> unit-phase features.
// Block = one row (512 threads). blockIdx.x < NROWS -> Q row, else K row.
// Output layout per row: [0..512]=cos(phase_f), [516..1028]=sin(phase_f),
// pads {513,514,515,1029,1030,1031} = 0.
// ---------------------------------------------------------------------------
__global__ __launch_bounds__(512) void fft_phase_kernel(
    const float* __restrict__ Q, const float* __restrict__ K)
{
    __shared__ float sr[1024];
    __shared__ float si[1024];
    __shared__ float wr[512];
    __shared__ float wi[512];

    const int t = threadIdx.x;        // 0..511
    const int rb = blockIdx.x;        // 0..2*NROWS-1
    const float* src;
    float* dst;
    if (rb < NROWS) {
        src = Q + (size_t)rb * HID;
        dst = g_Fq + (size_t)rb * KPAD;
    } else {
        int r = rb - NROWS;
        src = K + (size_t)r * HID;
        dst = g_Fk + (size_t)r * KPAD;
    }

    wr[t] = g_twr[t];
    wi[t] = g_twi[t];

    // Bit-reversed load (10-bit reversal), imag = 0
    {
        int i0 = t;
        int i1 = t + 512;
        sr[i0] = src[__brev((unsigned)i0) >> 22];
        si[i0] = 0.0f;
        sr[i1] = src[__brev((unsigned)i1) >> 22];
        si[i1] = 0.0f;
    }
    __syncthreads();

    // 10 DIT stages; each thread does one butterfly per stage
    #pragma unroll
    for (int s = 1; s <= 10; ++s) {
        const int half = 1 << (s - 1);
        const int pos  = t & (half - 1);
        const int i    = ((t >> (s - 1)) << s) + pos;
        const int j    = i + half;
        const int twi_ = pos << (10 - s);
        const float wre = wr[twi_];
        const float wim = wi[twi_];
        const float xr = sr[j], xi = si[j];
        const float tr = wre * xr - wim * xi;
        const float ti = wre * xi + wim * xr;
        const float ur = sr[i], ui = si[i];
        sr[j] = ur - tr;  si[j] = ui - ti;
        sr[i] = ur + tr;  si[i] = ui + ti;
        __syncthreads();
    }

    // Normalize to unit phase vectors: cos = Re/|X|, sin = Im/|X|
    {
        const float re = sr[t], im = si[t];
        const float m2 = re * re + im * im;
        float c, sn;
        if (m2 > 0.0f) {
            const float inv = rsqrtf(m2);
            c = re * inv; sn = im * inv;
        } else { c = 1.0f; sn = 0.0f; }   // atan2(0,0) = 0
        dst[t]          = c;
        dst[SINOFF + t] = sn;
    }
    if (t == 0) {  // f = 512 (Nyquist)
        const float re = sr[512], im = si[512];
        const float m2 = re * re + im * im;
        float c, sn;
        if (m2 > 0.0f) {
            const float inv = rsqrtf(m2);
            c = re * inv; sn = im * inv;
        } else { c = 1.0f; sn = 0.0f; }
        dst[512]          = c;
        dst[SINOFF + 512] = sn;
    }
    if (t < 3) {   // zero pads
        dst[513 + t]  = 0.0f;
        dst[1029 + t] = 0.0f;
    }
}

// ---------------------------------------------------------------------------
// GEMM 1 (NT): scores[b,i,j] = (1/513) * dot(Fq[b,i,:], Fk[b,j,:])
// 128x128 tile, BK=8, 8x8 per thread, 256 threads.
// ---------------------------------------------------------------------------
__global__ __launch_bounds__(256) void gemm_scores_kernel(float* __restrict__ Wout)
{
    const int bN = blockIdx.x;   // j tile
    const int bM = blockIdx.y;   // i tile
    const int b  = blockIdx.z;

    const float* A  = g_Fq + (size_t)b * SEQ * KPAD;
    const float* Bm = g_Fk + (size_t)b * SEQ * KPAD;
    float*       C  = Wout + (size_t)b * SEQ * SEQ;

    __shared__ float As[8][128];
    __shared__ float Bs[8][128];

    const int tid = threadIdx.x;
    const int tx  = tid & 15;       // 0..15 -> col group
    const int ty  = tid >> 4;       // 0..15 -> row group
    const int lr  = tid >> 1;       // 0..127 tile row to load
    const int lk  = (tid & 1) * 4;  // 0 or 4

    const float* aptr = A  + (size_t)(bM * 128 + lr) * KPAD + lk;
    const float* bptr = Bm + (size_t)(bN * 128 + lr) * KPAD + lk;

    float acc[8][8];
    #pragma unroll
    for (int m = 0; m < 8; ++m)
        #pragma unroll
        for (int n = 0; n < 8; ++n) acc[m][n] = 0.0f;

    for (int k0 = 0; k0 < KPAD; k0 += 8) {
        const float4 av = *(const float4*)(aptr + k0);
        const float4 bv = *(const float4*)(bptr + k0);
        __syncthreads();
        As[lk + 0][lr] = av.x; As[lk + 1][lr] = av.y;
        As[lk + 2][lr] = av.z; As[lk + 3][lr] = av.w;
        Bs[lk + 0][lr] = bv.x; Bs[lk + 1][lr] = bv.y;
        Bs[lk + 2][lr] = bv.z; Bs[lk + 3][lr] = bv.w;
        __syncthreads();
        #pragma unroll
        for (int kk = 0; kk < 8; ++kk) {
            const float4 a0 = *(const float4*)&As[kk][ty * 8];
            const float4 a1 = *(const float4*)&As[kk][ty * 8 + 4];
            const float4 b0 = *(const float4*)&Bs[kk][tx * 8];
            const float4 b1 = *(const float4*)&Bs[kk][tx * 8 + 4];
            const float ra[8] = {a0.x, a0.y, a0.z, a0.w, a1.x, a1.y, a1.z, a1.w};
            const float rbv[8] = {b0.x, b0.y, b0.z, b0.w, b1.x, b1.y, b1.z, b1.w};
            #pragma unroll
            for (int m = 0; m < 8; ++m)
                #pragma unroll
                for (int n = 0; n < 8; ++n)
                    acc[m][n] = fmaf(ra[m], rbv[n], acc[m][n]);
        }
    }

    const float scale = 1.0f / 513.0f;
    #pragma unroll
    for (int m = 0; m < 8; ++m) {
        const int row = bM * 128 + ty * 8 + m;
        float* cp = C + (size_t)row * SEQ + bN * 128 + tx * 8;
        float4 o0, o1;
        o0.x = acc[m][0] * scale; o0.y = acc[m][1] * scale;
        o0.z = acc[m][2] * scale; o0.w = acc[m][3] * scale;
        o1.x = acc[m][4] * scale; o1.y = acc[m][5] * scale;
        o1.z = acc[m][6] * scale; o1.w = acc[m][7] * scale;
        *(float4*)cp       = o0;
        *(float4*)(cp + 4) = o1;
    }
}

// ---------------------------------------------------------------------------
// In-place row softmax over SEQ=2048 (one block per row, 256 threads x 8 elems)
// ---------------------------------------------------------------------------
__global__ __launch_bounds__(256) void softmax_kernel(float* __restrict__ W)
{
    float* p = W + (size_t)blockIdx.x * SEQ;
    const int t = threadIdx.x;
    __shared__ float red[8];

    float4 v0 = *(float4*)(p + t * 8);
    float4 v1 = *(float4*)(p + t * 8 + 4);
    float v[8] = {v0.x, v0.y, v0.z, v0.w, v1.x, v1.y, v1.z, v1.w};

    // max reduce
    float mx = v[0];
    #pragma unroll
    for (int i = 1; i < 8; ++i) mx = fmaxf(mx, v[i]);
    #pragma unroll
    for (int o = 16; o > 0; o >>= 1) mx = fmaxf(mx, __shfl_xor_sync(0xFFFFFFFFu, mx, o));
    if ((t & 31) == 0) red[t >> 5] = mx;
    __syncthreads();
    if (t < 32) {
        float m = (t < 8) ? red[t] : -1e30f;
        #pragma unroll
        for (int o = 4; o > 0; o >>= 1) m = fmaxf(m, __shfl_xor_sync(0xFFFFFFFFu, m, o));
        if (t == 0) red[0] = m;
    }
    __syncthreads();
    mx = red[0];
    __syncthreads();

    // exp + sum reduce
    float sum = 0.0f;
    #pragma unroll
    for (int i = 0; i < 8; ++i) { v[i] = expf(v[i] - mx); sum += v[i]; }
    #pragma unroll
    for (int o = 16; o > 0; o >>= 1) sum += __shfl_xor_sync(0xFFFFFFFFu, sum, o);
    if ((t & 31) == 0) red[t >> 5] = sum;
    __syncthreads();
    if (t < 32) {
        float s = (t < 8) ? red[t] : 0.0f;
        #pragma unroll
        for (int o = 4; o > 0; o >>= 1) s += __shfl_xor_sync(0xFFFFFFFFu, s, o);
        if (t == 0) red[0] = s;
    }
    __syncthreads();
    const float inv = 1.0f / red[0];

    v0.x = v[0] * inv; v0.y = v[1] * inv; v0.z = v[2] * inv; v0.w = v[3] * inv;
    v1.x = v[4] * inv; v1.y = v[5] * inv; v1.z = v[6] * inv; v1.w = v[7] * inv;
    *(float4*)(p + t * 8)     = v0;
    *(float4*)(p + t * 8 + 4) = v1;
}

// ---------------------------------------------------------------------------
// GEMM 2 (NN): out[b,i,h] = sum_j W[b,i,j] * V[b,j,h]
// 128x128 tile, BK=8, 8x8 per thread, 256 threads.
// ---------------------------------------------------------------------------
__global__ __launch_bounds__(256) void gemm_out_kernel(
    const float* __restrict__ W, const float* __restrict__ V, float* __restrict__ O)
{
    const int bN = blockIdx.x;   // h tile (0..7)
    const int bM = blockIdx.y;   // i tile (0..15)
    const int b  = blockIdx.z;

    const float* A  = W + (size_t)b * SEQ * SEQ;
    const float* Bv = V + (size_t)b * SEQ * HID;
    float*       C  = O + (size_t)b * SEQ * HID;

    __shared__ float As[8][128];
    __shared__ float Bs[8][128];

    const int tid = threadIdx.x;
    const int tx  = tid & 15;
    const int ty  = tid >> 4;
    const int lr  = tid >> 1;        // A: tile row to load
    const int lk  = (tid & 1) * 4;   // A: k offset
    const int kr  = tid >> 5;        // B: k row (0..7)
    const int nc  = (tid & 31) * 4;  // B: col offset (0..124)

    const float* aptr = A  + (size_t)(bM * 128 + lr) * SEQ + lk;
    const float* bptr = Bv + (size_t)kr * HID + bN * 128 + nc;

    float acc[8][8];
    #pragma unroll
    for (int m = 0; m < 8; ++m)
        #pragma unroll
        for (int n = 0; n < 8; ++n) acc[m][n] = 0.0f;

    for (int k0 = 0; k0 < SEQ; k0 += 8) {
        const float4 av = *(const float4*)(aptr + k0);
        const float4 bv = *(const float4*)(bptr + (size_t)k0 * HID);
        __syncthreads();
        As[lk + 0][lr] = av.x; As[lk + 1][lr] = av.y;
        As[lk + 2][lr] = av.z; As[lk + 3][lr] = av.w;
        *(float4*)&Bs[kr][nc] = bv;
        __syncthreads();
        #pragma unroll
        for (int kk = 0; kk < 8; ++kk) {
            const float4 a0 = *(const float4*)&As[kk][ty * 8];
            const float4 a1 = *(const float4*)&As[kk][ty * 8 + 4];
            const float4 b0 = *(const float4*)&Bs[kk][tx * 8];
            const float4 b1 = *(const float4*)&Bs[kk][tx * 8 + 4];
            const float ra[8] = {a0.x, a0.y, a0.z, a0.w, a1.x, a1.y, a1.z, a1.w};
            const float rbv[8] = {b0.x, b0.y, b0.z, b0.w, b1.x, b1.y, b1.z, b1.w};
            #pragma unroll
            for (int m = 0; m < 8; ++m)
                #pragma unroll
                for (int n = 0; n < 8; ++n)
                    acc[m][n] = fmaf(ra[m], rbv[n], acc[m][n]);
        }
    }

    #pragma unroll
    for (int m = 0; m < 8; ++m) {
        const int row = bM * 128 + ty * 8 + m;
        float* cp = C + (size_t)row * HID + bN * 128 + tx * 8;
        float4 o0, o1;
        o0.x = acc[m][0]; o0.y = acc[m][1]; o0.z = acc[m][2]; o0.w = acc[m][3];
        o1.x = acc[m][4]; o1.y = acc[m][5]; o1.z = acc[m][6]; o1.w = acc[m][7];
        *(float4*)cp       = o0;
        *(float4*)(cp + 4) = o1;
    }
}

// ---------------------------------------------------------------------------
// Launch: FFT features -> scores GEMM -> softmax (in place) -> output GEMM
// d_out layout: [B*S*H output][B*S*S weights]
// ---------------------------------------------------------------------------
extern "C" void kernel_launch(void* const* d_in, const int* in_sizes, int n_in,
                              void* d_out, int out_size)
{
    const float* Q = (const float*)d_in[0];
    const float* K = (const float*)d_in[1];
    const float* V = (const float*)d_in[2];
    float* out = (float*)d_out;
    float* Wts = out + (size_t)NB * SEQ * HID;

    init_twiddles_kernel<<<1, 512>>>();
    fft_phase_kernel<<<2 * NROWS, 512>>>(Q, K);

    dim3 g1(SEQ / 128, SEQ / 128, NB);
    gemm_scores_kernel<<<g1, 256>>>(Wts);

    softmax_kernel<<<NROWS, 256>>>(Wts);

    dim3 g2(HID / 128, SEQ / 128, NB);
    gemm_out_kernel<<<g2, 256>>>(Wts, V, out);
}

// round 2
// speedup vs baseline: 2.0939x; 2.0939x over previous
#include <cuda_runtime.h>
#include <math.h>

// Problem constants
#define NB    4
#define SEQ   2048
#define HID   1024
#define NFREQ 513
#define KPAD  1040     // 513 cos + 7 pad + 513 sin + 7 pad (divisible by 16)
#define SINOFF 520
#define NROWS (NB*SEQ)

#define BK    8
#define PITCH 136      // smem pitch (floats); 136 % 32 == 8 -> conflict-free frags

// Scratch feature matrices
__device__ float g_Fq[(size_t)NROWS * KPAD];
__device__ float g_Fk[(size_t)NROWS * KPAD];
__device__ float g_twr[512];
__device__ float g_twi[512];

__device__ __forceinline__ unsigned f2tf32(float x) {
    unsigned r;
    asm("cvt.rna.tf32.f32 %0, %1;" : "=r"(r) : "f"(x));
    return r;
}

#define MMA_TF32(d, a, b) \
    asm volatile("mma.sync.aligned.m16n8k8.row.col.f32.tf32.tf32.f32 " \
        "{%0,%1,%2,%3}, {%4,%5,%6,%7}, {%8,%9}, {%0,%1,%2,%3};" \
        : "+f"(d[0]), "+f"(d[1]), "+f"(d[2]), "+f"(d[3]) \
        : "r"(a[0]), "r"(a[1]), "r"(a[2]), "r"(a[3]), "r"(b[0]), "r"(b[1]))

// ---------------------------------------------------------------------------
__global__ void init_twiddles_kernel() {
    int t = threadIdx.x;
    if (t < 512) {
        double ang = -2.0 * 3.141592653589793238462643 * (double)t / 1024.0;
        g_twr[t] = (float)cos(ang);
        g_twi[t] = (float)sin(ang);
    }
}

// ---------------------------------------------------------------------------
// Per-row 1024-pt radix-2 FFT -> unit phase features (cos @0, sin @SINOFF)
// ---------------------------------------------------------------------------
__global__ __launch_bounds__(512) void fft_phase_kernel(
    const float* __restrict__ Q, const float* __restrict__ K)
{
    __shared__ float sr[1024];
    __shared__ float si[1024];
    __shared__ float wr[512];
    __shared__ float wi[512];

    const int t = threadIdx.x;
    const int rb = blockIdx.x;
    const float* src;
    float* dst;
    if (rb < NROWS) {
        src = Q + (size_t)rb * HID;
        dst = g_Fq + (size_t)rb * KPAD;
    } else {
        int r = rb - NROWS;
        src = K + (size_t)r * HID;
        dst = g_Fk + (size_t)r * KPAD;
    }

    wr[t] = g_twr[t];
    wi[t] = g_twi[t];

    {
        int i0 = t, i1 = t + 512;
        sr[i0] = src[__brev((unsigned)i0) >> 22];
        si[i0] = 0.0f;
        sr[i1] = src[__brev((unsigned)i1) >> 22];
        si[i1] = 0.0f;
    }
    __syncthreads();

    #pragma unroll
    for (int s = 1; s <= 10; ++s) {
        const int half = 1 << (s - 1);
        const int pos  = t & (half - 1);
        const int i    = ((t >> (s - 1)) << s) + pos;
        const int j    = i + half;
        const int twi_ = pos << (10 - s);
        const float wre = wr[twi_];
        const float wim = wi[twi_];
        const float xr = sr[j], xi = si[j];
        const float tr = wre * xr - wim * xi;
        const float ti = wre * xi + wim * xr;
        const float ur = sr[i], ui = si[i];
        sr[j] = ur - tr;  si[j] = ui - ti;
        sr[i] = ur + tr;  si[i] = ui + ti;
        __syncthreads();
    }

    {
        const float re = sr[t], im = si[t];
        const float m2 = re * re + im * im;
        float c, sn;
        if (m2 > 0.0f) {
            const float inv = rsqrtf(m2);
            c = re * inv; sn = im * inv;
        } else { c = 1.0f; sn = 0.0f; }
        dst[t]          = c;
        dst[SINOFF + t] = sn;
    }
    if (t == 0) {
        const float re = sr[512], im = si[512];
        const float m2 = re * re + im * im;
        float c, sn;
        if (m2 > 0.0f) {
            const float inv = rsqrtf(m2);
            c = re * inv; sn = im * inv;
        } else { c = 1.0f; sn = 0.0f; }
        dst[512]          = c;
        dst[SINOFF + 512] = sn;
    }
    if (t < 7) {
        dst[513 + t]  = 0.0f;
        dst[1033 + t] = 0.0f;
    }
}

// ---------------------------------------------------------------------------
// GEMM 1 (NT, tf32 tensor cores): scores = (1/513) * Fq @ Fk^T
// 128x128 tile, BK=8, double buffered, 8 warps @ 32x64 warp tiles.
// ---------------------------------------------------------------------------
__global__ __launch_bounds__(256) void gemm_scores_tc(float* __restrict__ Wout)
{
    __shared__ unsigned As[2][BK][PITCH];
    __shared__ unsigned Bs[2][BK][PITCH];

    const int bN = blockIdx.x, bM = blockIdx.y, b = blockIdx.z;
    const float* A  = g_Fq + (size_t)b * SEQ * KPAD + (size_t)(bM * 128) * KPAD;
    const float* Bm = g_Fk + (size_t)b * SEQ * KPAD + (size_t)(bN * 128) * KPAD;
    float*       C  = Wout + (size_t)b * SEQ * SEQ;

    const int tid  = threadIdx.x;
    const int lane = tid & 31, wid = tid >> 5;
    const int wm = wid & 3, wn = wid >> 2;      // warp tile origin (wm*32, wn*64)
    const int g  = lane >> 2, tg = lane & 3;

    const int lrow = tid >> 1;                  // 0..127
    const int lk   = (tid & 1) * 4;             // 0 or 4

    const float* aptr = A  + (size_t)lrow * KPAD + lk;
    const float* bptr = Bm + (size_t)lrow * KPAD + lk;

    float acc[2][8][4];
    #pragma unroll
    for (int mt = 0; mt < 2; ++mt)
        #pragma unroll
        for (int nt = 0; nt < 8; ++nt)
            #pragma unroll
            for (int c = 0; c < 4; ++c) acc[mt][nt][c] = 0.0f;

    // prologue
    {
        float4 av = *(const float4*)aptr;
        float4 bv = *(const float4*)bptr;
        As[0][lk+0][lrow] = f2tf32(av.x); As[0][lk+1][lrow] = f2tf32(av.y);
        As[0][lk+2][lrow] = f2tf32(av.z); As[0][lk+3][lrow] = f2tf32(av.w);
        Bs[0][lk+0][lrow] = f2tf32(bv.x); Bs[0][lk+1][lrow] = f2tf32(bv.y);
        Bs[0][lk+2][lrow] = f2tf32(bv.z); Bs[0][lk+3][lrow] = f2tf32(bv.w);
    }
    __syncthreads();

    const int NIT = KPAD / BK;  // 130
    for (int it = 0; it < NIT; ++it) {
        const int buf = it & 1;
        float4 av, bv;
        if (it + 1 < NIT) {
            av = *(const float4*)(aptr + (it + 1) * BK);
            bv = *(const float4*)(bptr + (it + 1) * BK);
        }

        unsigned af[2][4], bf[8][2];
        #pragma unroll
        for (int mt = 0; mt < 2; ++mt) {
            const int r = wm * 32 + mt * 16 + g;
            af[mt][0] = As[buf][tg    ][r];
            af[mt][1] = As[buf][tg    ][r + 8];
            af[mt][2] = As[buf][tg + 4][r];
            af[mt][3] = As[buf][tg + 4][r + 8];
        }
        #pragma unroll
        for (int nt = 0; nt < 8; ++nt) {
            const int c0 = wn * 64 + nt * 8 + g;
            bf[nt][0] = Bs[buf][tg    ][c0];
            bf[nt][1] = Bs[buf][tg + 4][c0];
        }
        #pragma unroll
        for (int mt = 0; mt < 2; ++mt)
            #pragma unroll
            for (int nt = 0; nt < 8; ++nt)
                MMA_TF32(acc[mt][nt], af[mt], bf[nt]);

        if (it + 1 < NIT) {
            const int nb = buf ^ 1;
            As[nb][lk+0][lrow] = f2tf32(av.x); As[nb][lk+1][lrow] = f2tf32(av.y);
            As[nb][lk+2][lrow] = f2tf32(av.z); As[nb][lk+3][lrow] = f2tf32(av.w);
            Bs[nb][lk+0][lrow] = f2tf32(bv.x); Bs[nb][lk+1][lrow] = f2tf32(bv.y);
            Bs[nb][lk+2][lrow] = f2tf32(bv.z); Bs[nb][lk+3][lrow] = f2tf32(bv.w);
        }
        __syncthreads();
    }

    const float scale = 1.0f / 513.0f;
    #pragma unroll
    for (int mt = 0; mt < 2; ++mt) {
        #pragma unroll
        for (int nt = 0; nt < 8; ++nt) {
            const int row = bM * 128 + wm * 32 + mt * 16 + g;
            const int col = bN * 128 + wn * 64 + nt * 8 + 2 * tg;
            float2 lo = make_float2(acc[mt][nt][0] * scale, acc[mt][nt][1] * scale);
            float2 hi = make_float2(acc[mt][nt][2] * scale, acc[mt][nt][3] * scale);
            *(float2*)(C + (size_t)row * SEQ + col)       = lo;
            *(float2*)(C + (size_t)(row + 8) * SEQ + col) = hi;
        }
    }
}

// ---------------------------------------------------------------------------
// In-place row softmax over SEQ=2048
// ---------------------------------------------------------------------------
__global__ __launch_bounds__(256) void softmax_kernel(float* __restrict__ W)
{
    float* p = W + (size_t)blockIdx.x * SEQ;
    const int t = threadIdx.x;
    __shared__ float red[8];

    float4 v0 = *(float4*)(p + t * 8);
    float4 v1 = *(float4*)(p + t * 8 + 4);
    float v[8] = {v0.x, v0.y, v0.z, v0.w, v1.x, v1.y, v1.z, v1.w};

    float mx = v[0];
    #pragma unroll
    for (int i = 1; i < 8; ++i) mx = fmaxf(mx, v[i]);
    #pragma unroll
    for (int o = 16; o > 0; o >>= 1) mx = fmaxf(mx, __shfl_xor_sync(0xFFFFFFFFu, mx, o));
    if ((t & 31) == 0) red[t >> 5] = mx;
    __syncthreads();
    if (t < 32) {
        float m = (t < 8) ? red[t] : -1e30f;
        #pragma unroll
        for (int o = 4; o > 0; o >>= 1) m = fmaxf(m, __shfl_xor_sync(0xFFFFFFFFu, m, o));
        if (t == 0) red[0] = m;
    }
    __syncthreads();
    mx = red[0];
    __syncthreads();

    float sum = 0.0f;
    #pragma unroll
    for (int i = 0; i < 8; ++i) { v[i] = expf(v[i] - mx); sum += v[i]; }
    #pragma unroll
    for (int o = 16; o > 0; o >>= 1) sum += __shfl_xor_sync(0xFFFFFFFFu, sum, o);
    if ((t & 31) == 0) red[t >> 5] = sum;
    __syncthreads();
    if (t < 32) {
        float s = (t < 8) ? red[t] : 0.0f;
        #pragma unroll
        for (int o = 4; o > 0; o >>= 1) s += __shfl_xor_sync(0xFFFFFFFFu, s, o);
        if (t == 0) red[0] = s;
    }
    __syncthreads();
    const float inv = 1.0f / red[0];

    v0.x = v[0]*inv; v0.y = v[1]*inv; v0.z = v[2]*inv; v0.w = v[3]*inv;
    v1.x = v[4]*inv; v1.y = v[5]*inv; v1.z = v[6]*inv; v1.w = v[7]*inv;
    *(float4*)(p + t * 8)     = v0;
    *(float4*)(p + t * 8 + 4) = v1;
}

// ---------------------------------------------------------------------------
// GEMM 2 (NN, tf32 tensor cores): out = W @ V
// ---------------------------------------------------------------------------
__global__ __launch_bounds__(256) void gemm_out_tc(
    const float* __restrict__ W, const float* __restrict__ V, float* __restrict__ O)
{
    __shared__ unsigned As[2][BK][PITCH];
    __shared__ unsigned Bs[2][BK][PITCH];

    const int bN = blockIdx.x, bM = blockIdx.y, b = blockIdx.z;
    const float* A  = W + (size_t)b * SEQ * SEQ + (size_t)(bM * 128) * SEQ;
    const float* Bv = V + (size_t)b * SEQ * HID + bN * 128;
    float*       C  = O + (size_t)b * SEQ * HID;

    const int tid  = threadIdx.x;
    const int lane = tid & 31, wid = tid >> 5;
    const int wm = wid & 3, wn = wid >> 2;
    const int g  = lane >> 2, tg = lane & 3;

    const int lrow = tid >> 1;
    const int lk   = (tid & 1) * 4;
    const int bk_k = tid >> 5;          // 0..7  (k row for B tile)
    const int bk_n = (tid & 31) * 4;    // 0..124

    const float* aptr = A + (size_t)lrow * SEQ + lk;
    const float* bptr = Bv + (size_t)bk_k * HID + bk_n;

    float acc[2][8][4];
    #pragma unroll
    for (int mt = 0; mt < 2; ++mt)
        #pragma unroll
        for (int nt = 0; nt < 8; ++nt)
            #pragma unroll
            for (int c = 0; c < 4; ++c) acc[mt][nt][c] = 0.0f;

    {
        float4 av = *(const float4*)aptr;
        float4 bv = *(const float4*)bptr;
        As[0][lk+0][lrow] = f2tf32(av.x); As[0][lk+1][lrow] = f2tf32(av.y);
        As[0][lk+2][lrow] = f2tf32(av.z); As[0][lk+3][lrow] = f2tf32(av.w);
        uint4 bo;
        bo.x = f2tf32(bv.x); bo.y = f2tf32(bv.y); bo.z = f2tf32(bv.z); bo.w = f2tf32(bv.w);
        *(uint4*)&Bs[0][bk_k][bk_n] = bo;
    }
    __syncthreads();

    const int NIT = SEQ / BK;  // 256
    for (int it = 0; it < NIT; ++it) {
        const int buf = it & 1;
        float4 av, bv;
        if (it + 1 < NIT) {
            av = *(const float4*)(aptr + (it + 1) * BK);
            bv = *(const float4*)(bptr + (size_t)(it + 1) * BK * HID);
        }

        unsigned af[2][4], bf[8][2];
        #pragma unroll
        for (int mt = 0; mt < 2; ++mt) {
            const int r = wm * 32 + mt * 16 + g;
            af[mt][0] = As[buf][tg    ][r];
            af[mt][1] = As[buf][tg    ][r + 8];
            af[mt][2] = As[buf][tg + 4][r];
            af[mt][3] = As[buf][tg + 4][r + 8];
        }
        #pragma unroll
        for (int nt = 0; nt < 8; ++nt) {
            const int c0 = wn * 64 + nt * 8 + g;
            bf[nt][0] = Bs[buf][tg    ][c0];
            bf[nt][1] = Bs[buf][tg + 4][c0];
        }
        #pragma unroll
        for (int mt = 0; mt < 2; ++mt)
            #pragma unroll
            for (int nt = 0; nt < 8; ++nt)
                MMA_TF32(acc[mt][nt], af[mt], bf[nt]);

        if (it + 1 < NIT) {
            const int nb = buf ^ 1;
            As[nb][lk+0][lrow] = f2tf32(av.x); As[nb][lk+1][lrow] = f2tf32(av.y);
            As[nb][lk+2][lrow] = f2tf32(av.z); As[nb][lk+3][lrow] = f2tf32(av.w);
            uint4 bo;
            bo.x = f2tf32(bv.x); bo.y = f2tf32(bv.y); bo.z = f2tf32(bv.z); bo.w = f2tf32(bv.w);
            *(uint4*)&Bs[nb][bk_k][bk_n] = bo;
        }
        __syncthreads();
    }

    #pragma unroll
    for (int mt = 0; mt < 2; ++mt) {
        #pragma unroll
        for (int nt = 0; nt < 8; ++nt) {
            const int row = bM * 128 + wm * 32 + mt * 16 + g;
            const int col = bN * 128 + wn * 64 + nt * 8 + 2 * tg;
            float2 lo = make_float2(acc[mt][nt][0], acc[mt][nt][1]);
            float2 hi = make_float2(acc[mt][nt][2], acc[mt][nt][3]);
            *(float2*)(C + (size_t)row * HID + col)       = lo;
            *(float2*)(C + (size_t)(row + 8) * HID + col) = hi;
        }
    }
}

// ---------------------------------------------------------------------------
extern "C" void kernel_launch(void* const* d_in, const int* in_sizes, int n_in,
                              void* d_out, int out_size)
{
    const float* Q = (const float*)d_in[0];
    const float* K = (const float*)d_in[1];
    const float* V = (const float*)d_in[2];
    float* out = (float*)d_out;
    float* Wts = out + (size_t)NB * SEQ * HID;

    init_twiddles_kernel<<<1, 512>>>();
    fft_phase_kernel<<<2 * NROWS, 512>>>(Q, K);

    dim3 g1(SEQ / 128, SEQ / 128, NB);
    gemm_scores_tc<<<g1, 256>>>(Wts);

    softmax_kernel<<<NROWS, 256>>>(Wts);

    dim3 g2(HID / 128, SEQ / 128, NB);
    gemm_out_tc<<<g2, 256>>>(Wts, V, out);
}

// round 4
// speedup vs baseline: 2.3770x; 1.1352x over previous
#include <cuda_runtime.h>
#include <math.h>

// Problem constants
#define NB    4
#define SEQ   2048
#define HID   1024
#define NFREQ 513
#define KPAD  1040     // 513 cos + 7 pad + 513 sin + 7 pad
#define SINOFF 520
#define NROWS (NB*SEQ)

#define BK    8
#define APITCH 12      // A/B tile pitch (floats): conflict-free frag loads, 48B rows
#define BPITCH 136     // GEMM2 B tile pitch: 544B rows, conflict-free

// Scratch feature matrices
__device__ float g_Fq[(size_t)NROWS * KPAD];
__device__ float g_Fk[(size_t)NROWS * KPAD];
__device__ float g_twr[512];
__device__ float g_twi[512];

__device__ __forceinline__ unsigned f2tf32(float x) {
    unsigned r;
    asm("cvt.rna.tf32.f32 %0, %1;" : "=r"(r) : "f"(x));
    return r;
}

__device__ __forceinline__ unsigned smem_u32(const void* p) {
    return (unsigned)__cvta_generic_to_shared(p);
}

#define CP_ASYNC16(dst, src) \
    asm volatile("cp.async.cg.shared.global [%0], [%1], 16;" :: "r"(dst), "l"(src))
#define CP_COMMIT() asm volatile("cp.async.commit_group;")
#define CP_WAIT1()  asm volatile("cp.async.wait_group 1;")
#define CP_WAIT0()  asm volatile("cp.async.wait_group 0;")

#define MMA_TF32(d, a, b) \
    asm volatile("mma.sync.aligned.m16n8k8.row.col.f32.tf32.tf32.f32 " \
        "{%0,%1,%2,%3}, {%4,%5,%6,%7}, {%8,%9}, {%0,%1,%2,%3};" \
        : "+f"(d[0]), "+f"(d[1]), "+f"(d[2]), "+f"(d[3]) \
        : "r"(a[0]), "r"(a[1]), "r"(a[2]), "r"(a[3]), "r"(b[0]), "r"(b[1]))

// ---------------------------------------------------------------------------
__global__ void init_twiddles_kernel() {
    int t = threadIdx.x;
    if (t < 512) {
        double ang = -2.0 * 3.141592653589793238462643 * (double)t / 1024.0;
        g_twr[t] = (float)cos(ang);
        g_twi[t] = (float)sin(ang);
    }
}

// ---------------------------------------------------------------------------
// Per-row 1024-pt radix-4 FFT (5 stages) -> unit phase features.
// 256 threads/block, one radix-4 butterfly per thread per stage.
// ---------------------------------------------------------------------------
__global__ __launch_bounds__(256) void fft_phase_kernel(
    const float* __restrict__ Q, const float* __restrict__ K)
{
    __shared__ float sr[1024];
    __shared__ float si[1024];
    __shared__ float wr[256];
    __shared__ float wi[256];

    const int t = threadIdx.x;       // 0..255
    const int rb = blockIdx.x;
    const float* src;
    float* dst;
    if (rb < NROWS) {
        src = Q + (size_t)rb * HID;
        dst = g_Fq + (size_t)rb * KPAD;
    } else {
        int r = rb - NROWS;
        src = K + (size_t)r * HID;
        dst = g_Fk + (size_t)r * KPAD;
    }

    wr[t] = g_twr[t];
    wi[t] = g_twi[t];

    // Base-4 digit-reversed load (bit-reverse 10 bits, then swap bit pairs)
    #pragma unroll
    for (int l = 0; l < 4; ++l) {
        const int j = t + 256 * l;
        const unsigned r2 = __brev((unsigned)j) >> 22;
        const unsigned dr = ((r2 & 0x155u) << 1) | ((r2 & 0x2AAu) >> 1);
        sr[j] = src[dr];
        si[j] = 0.0f;
    }
    __syncthreads();

    // 5 radix-4 DIT stages
    #pragma unroll
    for (int s = 0; s < 5; ++s) {
        const int quarter = 1 << (2 * s);
        const int pos = t & (quarter - 1);
        const int grp = t >> (2 * s);
        const int i0  = grp * (quarter << 2) + pos;
        const int e   = pos << (8 - 2 * s);   // exponent for w1, e < 256

        const float w1r = wr[e],  w1i = wi[e];
        const float w2r = w1r * w1r - w1i * w1i;
        const float w2i = 2.0f * w1r * w1i;
        const float w3r = w2r * w1r - w2i * w1i;
        const float w3i = w2r * w1i + w2i * w1r;

        const int i1 = i0 + quarter, i2 = i1 + quarter, i3 = i2 + quarter;
        const float x0r = sr[i0], x0i = si[i0];
        const float x1r = sr[i1], x1i = si[i1];
        const float x2r = sr[i2], x2i = si[i2];
        const float x3r = sr[i3], x3i = si[i3];

        const float t1r = w1r * x1r - w1i * x1i, t1i = w1r * x1i + w1i * x1r;
        const float t2r = w2r * x2r - w2i * x2i, t2i = w2r * x2i + w2i * x2r;
        const float t3r = w3r * x3r - w3i * x3i, t3i = w3r * x3i + w3i * x3r;

        const float ar = x0r + t2r, ai = x0i + t2i;   // t0 + t2
        const float br = x0r - t2r, bi = x0i - t2i;   // t0 - t2
        const float cr = t1r + t3r, ci = t1i + t3i;   // t1 + t3
        const float dr = t1r - t3r, di = t1i - t3i;   // t1 - t3

        sr[i0] = ar + cr;  si[i0] = ai + ci;
        sr[i2] = ar - cr;  si[i2] = ai - ci;
        sr[i1] = br + di;  si[i1] = bi - dr;          // -i * d
        sr[i3] = br - di;  si[i3] = bi + dr;          // +i * d
        __syncthreads();
    }

    // Normalize to unit phase: cos = Re/|X|, sin = Im/|X|
    #pragma unroll
    for (int l = 0; l < 2; ++l) {
        const int f = t + 256 * l;     // 0..511
        const float re = sr[f], im = si[f];
        const float m2 = re * re + im * im;
        float c, sn;
        if (m2 > 0.0f) {
            const float inv = rsqrtf(m2);
            c = re * inv; sn = im * inv;
        } else { c = 1.0f; sn = 0.0f; }
        dst[f]          = c;
        dst[SINOFF + f] = sn;
    }
    if (t == 0) {
        const float re = sr[512], im = si[512];
        const float m2 = re * re + im * im;
        float c, sn;
        if (m2 > 0.0f) {
            const float inv = rsqrtf(m2);
            c = re * inv; sn = im * inv;
        } else { c = 1.0f; sn = 0.0f; }
        dst[512]          = c;
        dst[SINOFF + 512] = sn;
    }
    if (t < 7) {
        dst[513 + t]  = 0.0f;
        dst[1033 + t] = 0.0f;
    }
}

// ---------------------------------------------------------------------------
// GEMM 1 (NT, tf32): scores = (1/513) * Fq @ Fk^T
// 128x128 tile, BK=8, 3-stage cp.async pipeline, one sync per iter.
// Smem tiles row-major [128][APITCH]; tf32 cvt at fragment load.
// ---------------------------------------------------------------------------
__global__ __launch_bounds__(256) void gemm_scores_tc(float* __restrict__ Wout)
{
    __shared__ float As[3][128][APITCH];
    __shared__ float Bs[3][128][APITCH];

    const int bN = blockIdx.x, bM = blockIdx.y, b = blockIdx.z;
    const float* A  = g_Fq + (size_t)b * SEQ * KPAD + (size_t)(bM * 128) * KPAD;
    const float* Bm = g_Fk + (size_t)b * SEQ * KPAD + (size_t)(bN * 128) * KPAD;
    float*       C  = Wout + (size_t)b * SEQ * SEQ;

    const int tid  = threadIdx.x;
    const int lane = tid & 31, wid = tid >> 5;
    const int wm = wid & 3, wn = wid >> 2;
    const int g  = lane >> 2, tg = lane & 3;

    const int lrow   = tid >> 1;          // 0..127
    const int lchunk = (tid & 1) * 4;     // 0 or 4

    const float* ag = A  + (size_t)lrow * KPAD + lchunk;
    const float* bg = Bm + (size_t)lrow * KPAD + lchunk;
    const unsigned a_s[3] = { smem_u32(&As[0][lrow][lchunk]), smem_u32(&As[1][lrow][lchunk]), smem_u32(&As[2][lrow][lchunk]) };
    const unsigned b_s[3] = { smem_u32(&Bs[0][lrow][lchunk]), smem_u32(&Bs[1][lrow][lchunk]), smem_u32(&Bs[2][lrow][lchunk]) };

    float acc[2][8][4];
    #pragma unroll
    for (int mt = 0; mt < 2; ++mt)
        #pragma unroll
        for (int nt = 0; nt < 8; ++nt)
            #pragma unroll
            for (int c = 0; c < 4; ++c) acc[mt][nt][c] = 0.0f;

    const int NIT = KPAD / BK;  // 130
    // prologue: stages 0,1
    #pragma unroll
    for (int s = 0; s < 2; ++s) {
        CP_ASYNC16(a_s[s], ag + s * BK);
        CP_ASYNC16(b_s[s], bg + s * BK);
        CP_COMMIT();
    }

    for (int it = 0; it < NIT; ++it) {
        const int buf = it % 3;
        if (it + 2 < NIT)      CP_WAIT1();
        else                   CP_WAIT0();
        __syncthreads();

        const int nxt = it + 2;
        if (nxt < NIT) {
            const int nb = nxt % 3;
            CP_ASYNC16(a_s[nb], ag + nxt * BK);
            CP_ASYNC16(b_s[nb], bg + nxt * BK);
            CP_COMMIT();
        }

        unsigned af[2][4], bf[8][2];
        #pragma unroll
        for (int mt = 0; mt < 2; ++mt) {
            const int r = wm * 32 + mt * 16 + g;
            af[mt][0] = f2tf32(As[buf][r    ][tg    ]);
            af[mt][1] = f2tf32(As[buf][r + 8][tg    ]);
            af[mt][2] = f2tf32(As[buf][r    ][tg + 4]);
            af[mt][3] = f2tf32(As[buf][r + 8][tg + 4]);
        }
        #pragma unroll
        for (int nt = 0; nt < 8; ++nt) {
            const int c0 = wn * 64 + nt * 8 + g;
            bf[nt][0] = f2tf32(Bs[buf][c0][tg    ]);
            bf[nt][1] = f2tf32(Bs[buf][c0][tg + 4]);
        }
        #pragma unroll
        for (int mt = 0; mt < 2; ++mt)
            #pragma unroll
            for (int nt = 0; nt < 8; ++nt)
                MMA_TF32(acc[mt][nt], af[mt], bf[nt]);
    }

    const float scale = 1.0f / 513.0f;
    #pragma unroll
    for (int mt = 0; mt < 2; ++mt) {
        #pragma unroll
        for (int nt = 0; nt < 8; ++nt) {
            const int row = bM * 128 + wm * 32 + mt * 16 + g;
            const int col = bN * 128 + wn * 64 + nt * 8 + 2 * tg;
            float2 lo = make_float2(acc[mt][nt][0] * scale, acc[mt][nt][1] * scale);
            float2 hi = make_float2(acc[mt][nt][2] * scale, acc[mt][nt][3] * scale);
            *(float2*)(C + (size_t)row * SEQ + col)       = lo;
            *(float2*)(C + (size_t)(row + 8) * SEQ + col) = hi;
        }
    }
}

// ---------------------------------------------------------------------------
// In-place row softmax over SEQ=2048
// ---------------------------------------------------------------------------
__global__ __launch_bounds__(256) void softmax_kernel(float* __restrict__ W)
{
    float* p = W + (size_t)blockIdx.x * SEQ;
    const int t = threadIdx.x;
    __shared__ float red[8];

    float4 v0 = *(float4*)(p + t * 8);
    float4 v1 = *(float4*)(p + t * 8 + 4);
    float v[8] = {v0.x, v0.y, v0.z, v0.w, v1.x, v1.y, v1.z, v1.w};

    float mx = v[0];
    #pragma unroll
    for (int i = 1; i < 8; ++i) mx = fmaxf(mx, v[i]);
    #pragma unroll
    for (int o = 16; o > 0; o >>= 1) mx = fmaxf(mx, __shfl_xor_sync(0xFFFFFFFFu, mx, o));
    if ((t & 31) == 0) red[t >> 5] = mx;
    __syncthreads();
    if (t < 32) {
        float m = (t < 8) ? red[t] : -1e30f;
        #pragma unroll
        for (int o = 4; o > 0; o >>= 1) m = fmaxf(m, __shfl_xor_sync(0xFFFFFFFFu, m, o));
        if (t == 0) red[0] = m;
    }
    __syncthreads();
    mx = red[0];
    __syncthreads();

    float sum = 0.0f;
    #pragma unroll
    for (int i = 0; i < 8; ++i) { v[i] = expf(v[i] - mx); sum += v[i]; }
    #pragma unroll
    for (int o = 16; o > 0; o >>= 1) sum += __shfl_xor_sync(0xFFFFFFFFu, sum, o);
    if ((t & 31) == 0) red[t >> 5] = sum;
    __syncthreads();
    if (t < 32) {
        float s = (t < 8) ? red[t] : 0.0f;
        #pragma unroll
        for (int o = 4; o > 0; o >>= 1) s += __shfl_xor_sync(0xFFFFFFFFu, s, o);
        if (t == 0) red[0] = s;
    }
    __syncthreads();
    const float inv = 1.0f / red[0];

    v0.x = v[0]*inv; v0.y = v[1]*inv; v0.z = v[2]*inv; v0.w = v[3]*inv;
    v1.x = v[4]*inv; v1.y = v[5]*inv; v1.z = v[6]*inv; v1.w = v[7]*inv;
    *(float4*)(p + t * 8)     = v0;
    *(float4*)(p + t * 8 + 4) = v1;
}

// ---------------------------------------------------------------------------
// GEMM 2 (NN, tf32): out = W @ V
// A tile [128][APITCH] (k-contig rows), B tile [BK][BPITCH] (n-contig rows).
// ---------------------------------------------------------------------------
__global__ __launch_bounds__(256) void gemm_out_tc(
    const float* __restrict__ W, const float* __restrict__ V, float* __restrict__ O)
{
    __shared__ float As[3][128][APITCH];
    __shared__ float Bs[3][BK][BPITCH];

    const int bN = blockIdx.x, bM = blockIdx.y, b = blockIdx.z;
    const float* A  = W + (size_t)b * SEQ * SEQ + (size_t)(bM * 128) * SEQ;
    const float* Bv = V + (size_t)b * SEQ * HID + bN * 128;
    float*       C  = O + (size_t)b * SEQ * HID;

    const int tid  = threadIdx.x;
    const int lane = tid & 31, wid = tid >> 5;
    const int wm = wid & 3, wn = wid >> 2;
    const int g  = lane >> 2, tg = lane & 3;

    const int lrow   = tid >> 1;
    const int lchunk = (tid & 1) * 4;
    const int brow   = tid >> 5;          // 0..7
    const int bcol   = (tid & 31) * 4;    // 0..124

    const float* ag = A  + (size_t)lrow * SEQ + lchunk;
    const float* bg = Bv + (size_t)brow * HID + bcol;
    const unsigned a_s[3] = { smem_u32(&As[0][lrow][lchunk]), smem_u32(&As[1][lrow][lchunk]), smem_u32(&As[2][lrow][lchunk]) };
    const unsigned b_s[3] = { smem_u32(&Bs[0][brow][bcol]), smem_u32(&Bs[1][brow][bcol]), smem_u32(&Bs[2][brow][bcol]) };

    float acc[2][8][4];
    #pragma unroll
    for (int mt = 0; mt < 2; ++mt)
        #pragma unroll
        for (int nt = 0; nt < 8; ++nt)
            #pragma unroll
            for (int c = 0; c < 4; ++c) acc[mt][nt][c] = 0.0f;

    const int NIT = SEQ / BK;  // 256
    #pragma unroll
    for (int s = 0; s < 2; ++s) {
        CP_ASYNC16(a_s[s], ag + s * BK);
        CP_ASYNC16(b_s[s], bg + (size_t)s * BK * HID);
        CP_COMMIT();
    }

    for (int it = 0; it < NIT; ++it) {
        const int buf = it % 3;
        if (it + 2 < NIT)      CP_WAIT1();
        else                   CP_WAIT0();
        __syncthreads();

        const int nxt = it + 2;
        if (nxt < NIT) {
            const int nb = nxt % 3;
            CP_ASYNC16(a_s[nb], ag + nxt * BK);
            CP_ASYNC16(b_s[nb], bg + (size_t)nxt * BK * HID);
            CP_COMMIT();
        }

        unsigned af[2][4], bf[8][2];
        #pragma unroll
        for (int mt = 0; mt < 2; ++mt) {
            const int r = wm * 32 + mt * 16 + g;
            af[mt][0] = f2tf32(As[buf][r    ][tg    ]);
            af[mt][1] = f2tf32(As[buf][r + 8][tg    ]);
            af[mt][2] = f2tf32(As[buf][r    ][tg + 4]);
            af[mt][3] = f2tf32(As[buf][r + 8][tg + 4]);
        }
        #pragma unroll
        for (int nt = 0; nt < 8; ++nt) {
            const int c0 = wn * 64 + nt * 8 + g;
            bf[nt][0] = f2tf32(Bs[buf][tg    ][c0]);
            bf[nt][1] = f2tf32(Bs[buf][tg + 4][c0]);
        }
        #pragma unroll
        for (int mt = 0; mt < 2; ++mt)
            #pragma unroll
            for (int nt = 0; nt < 8; ++nt)
                MMA_TF32(acc[mt][nt], af[mt], bf[nt]);
    }

    #pragma unroll
    for (int mt = 0; mt < 2; ++mt) {
        #pragma unroll
        for (int nt = 0; nt < 8; ++nt) {
            const int row = bM * 128 + wm * 32 + mt * 16 + g;
            const int col = bN * 128 + wn * 64 + nt * 8 + 2 * tg;
            float2 lo = make_float2(acc[mt][nt][0], acc[mt][nt][1]);
            float2 hi = make_float2(acc[mt][nt][2], acc[mt][nt][3]);
            *(float2*)(C + (size_t)row * HID + col)       = lo;
            *(float2*)(C + (size_t)(row + 8) * HID + col) = hi;
        }
    }
}

// ---------------------------------------------------------------------------
extern "C" void kernel_launch(void* const* d_in, const int* in_sizes, int n_in,
                              void* d_out, int out_size)
{
    const float* Q = (const float*)d_in[0];
    const float* K = (const float*)d_in[1];
    const float* V = (const float*)d_in[2];
    float* out = (float*)d_out;
    float* Wts = out + (size_t)NB * SEQ * HID;

    init_twiddles_kernel<<<1, 512>>>();
    fft_phase_kernel<<<2 * NROWS, 256>>>(Q, K);

    dim3 g1(SEQ / 128, SEQ / 128, NB);
    gemm_scores_tc<<<g1, 256>>>(Wts);

    softmax_kernel<<<NROWS, 256>>>(Wts);

    dim3 g2(HID / 128, SEQ / 128, NB);
    gemm_out_tc<<<g2, 256>>>(Wts, V, out);
}

// round 7
// speedup vs baseline: 2.6534x; 1.1163x over previous
#include <cuda_runtime.h>
#include <math.h>

// Problem constants
#define NB    4
#define SEQ   2048
#define HID   1024
#define NFREQ 513
#define KPAD  1040     // 513 cos + 7 pad + 513 sin + 7 pad
#define SINOFF 520
#define NROWS (NB*SEQ)

#define BK     16
#define APITCH 20      // tile pitch (floats): conflict-free frag loads
#define BPITCH 136     // GEMM2 B tile pitch (n-major rows)

// Scratch (values pre-rounded to tf32 where used as MMA operands)
__device__ float g_Fq[(size_t)NROWS * KPAD];
__device__ float g_Fk[(size_t)NROWS * KPAD];
__device__ float g_Wt[(size_t)NROWS * SEQ];          // tf32 copy of weights
__device__ float g_Vt[(size_t)NB * SEQ * HID];       // tf32 copy of V
__device__ float g_twr[256];
__device__ float g_twi[256];

__device__ __forceinline__ unsigned f2tf32(float x) {
    unsigned r;
    asm("cvt.rna.tf32.f32 %0, %1;" : "=r"(r) : "f"(x));
    return r;
}
__device__ __forceinline__ float f2tf32f(float x) {
    return __uint_as_float(f2tf32(x));
}
__device__ __forceinline__ unsigned smem_u32(const void* p) {
    return (unsigned)__cvta_generic_to_shared(p);
}

#define CP_ASYNC16(dst, src) \
    asm volatile("cp.async.cg.shared.global [%0], [%1], 16;" :: "r"(dst), "l"(src))
#define CP_COMMIT() asm volatile("cp.async.commit_group;")
#define CP_WAIT0()  asm volatile("cp.async.wait_group 0;")

#define MMA_TF32(d, a, b) \
    asm volatile("mma.sync.aligned.m16n8k8.row.col.f32.tf32.tf32.f32 " \
        "{%0,%1,%2,%3}, {%4,%5,%6,%7}, {%8,%9}, {%0,%1,%2,%3};" \
        : "+f"(d[0]), "+f"(d[1]), "+f"(d[2]), "+f"(d[3]) \
        : "r"(a[0]), "r"(a[1]), "r"(a[2]), "r"(a[3]), "r"(b[0]), "r"(b[1]))

// ---------------------------------------------------------------------------
__global__ void init_twiddles_kernel() {
    int t = threadIdx.x;
    if (t < 256) {
        double ang = -2.0 * 3.141592653589793238462643 * (double)t / 1024.0;
        g_twr[t] = (float)cos(ang);
        g_twi[t] = (float)sin(ang);
    }
}

// ---------------------------------------------------------------------------
// V -> tf32 pre-convert (one float4 per thread)
// ---------------------------------------------------------------------------
__global__ __launch_bounds__(256) void vconv_kernel(const float* __restrict__ V)
{
    const size_t i = ((size_t)blockIdx.x * 256 + threadIdx.x) * 4;
    float4 v = *(const float4*)(V + i);
    v.x = f2tf32f(v.x); v.y = f2tf32f(v.y);
    v.z = f2tf32f(v.z); v.w = f2tf32f(v.w);
    *(float4*)(g_Vt + i) = v;
}

// ---------------------------------------------------------------------------
// Per-row 1024-pt radix-4 FFT (5 stages) -> unit phase features (tf32-rounded)
// ---------------------------------------------------------------------------
__global__ __launch_bounds__(256) void fft_phase_kernel(
    const float* __restrict__ Q, const float* __restrict__ K)
{
    __shared__ float sr[1024];
    __shared__ float si[1024];
    __shared__ float wr[256];
    __shared__ float wi[256];

    const int t = threadIdx.x;
    const int rb = blockIdx.x;
    const float* src;
    float* dst;
    if (rb < NROWS) {
        src = Q + (size_t)rb * HID;
        dst = g_Fq + (size_t)rb * KPAD;
    } else {
        int r = rb - NROWS;
        src = K + (size_t)r * HID;
        dst = g_Fk + (size_t)r * KPAD;
    }

    wr[t] = g_twr[t];
    wi[t] = g_twi[t];

    #pragma unroll
    for (int l = 0; l < 4; ++l) {
        const int j = t + 256 * l;
        const unsigned r2 = __brev((unsigned)j) >> 22;
        const unsigned dr = ((r2 & 0x155u) << 1) | ((r2 & 0x2AAu) >> 1);
        sr[j] = src[dr];
        si[j] = 0.0f;
    }
    __syncthreads();

    #pragma unroll
    for (int s = 0; s < 5; ++s) {
        const int quarter = 1 << (2 * s);
        const int pos = t & (quarter - 1);
        const int grp = t >> (2 * s);
        const int i0  = grp * (quarter << 2) + pos;
        const int e   = pos << (8 - 2 * s);

        const float w1r = wr[e],  w1i = wi[e];
        const float w2r = w1r * w1r - w1i * w1i;
        const float w2i = 2.0f * w1r * w1i;
        const float w3r = w2r * w1r - w2i * w1i;
        const float w3i = w2r * w1i + w2i * w1r;

        const int i1 = i0 + quarter, i2 = i1 + quarter, i3 = i2 + quarter;
        const float x0r = sr[i0], x0i = si[i0];
        const float x1r = sr[i1], x1i = si[i1];
        const float x2r = sr[i2], x2i = si[i2];
        const float x3r = sr[i3], x3i = si[i3];

        const float t1r = w1r * x1r - w1i * x1i, t1i = w1r * x1i + w1i * x1r;
        const float t2r = w2r * x2r - w2i * x2i, t2i = w2r * x2i + w2i * x2r;
        const float t3r = w3r * x3r - w3i * x3i, t3i = w3r * x3i + w3i * x3r;

        const float ar = x0r + t2r, ai = x0i + t2i;
        const float br = x0r - t2r, bi = x0i - t2i;
        const float cr = t1r + t3r, ci = t1i + t3i;
        const float dr = t1r - t3r, di = t1i - t3i;

        sr[i0] = ar + cr;  si[i0] = ai + ci;
        sr[i2] = ar - cr;  si[i2] = ai - ci;
        sr[i1] = br + di;  si[i1] = bi - dr;
        sr[i3] = br - di;  si[i3] = bi + dr;
        __syncthreads();
    }

    #pragma unroll
    for (int l = 0; l < 2; ++l) {
        const int f = t + 256 * l;
        const float re = sr[f], im = si[f];
        const float m2 = re * re + im * im;
        float c, sn;
        if (m2 > 0.0f) {
            const float inv = rsqrtf(m2);
            c = re * inv; sn = im * inv;
        } else { c = 1.0f; sn = 0.0f; }
        dst[f]          = f2tf32f(c);
        dst[SINOFF + f] = f2tf32f(sn);
    }
    if (t == 0) {
        const float re = sr[512], im = si[512];
        const float m2 = re * re + im * im;
        float c, sn;
        if (m2 > 0.0f) {
            const float inv = rsqrtf(m2);
            c = re * inv; sn = im * inv;
        } else { c = 1.0f; sn = 0.0f; }
        dst[512]          = f2tf32f(c);
        dst[SINOFF + 512] = f2tf32f(sn);
    }
    if (t < 7) {
        dst[513 + t]  = 0.0f;
        dst[1033 + t] = 0.0f;
    }
}

// ---------------------------------------------------------------------------
// GEMM 1 (NT, tf32): scores = (1/513) * Fq @ Fk^T
// 128x128 tile, BK=16, 2-stage cp.async double buffer, static smem (40,960 B)
// Each thread fills 8 contiguous floats of its row: cp at +0B and +16B.
// ---------------------------------------------------------------------------
__global__ __launch_bounds__(256) void gemm_scores_tc(float* __restrict__ Wout)
{
    __shared__ float As[2][128][APITCH];
    __shared__ float Bs[2][128][APITCH];

    const int bN = blockIdx.x, bM = blockIdx.y, b = blockIdx.z;
    const float* A  = g_Fq + (size_t)b * SEQ * KPAD + (size_t)(bM * 128) * KPAD;
    const float* Bm = g_Fk + (size_t)b * SEQ * KPAD + (size_t)(bN * 128) * KPAD;
    float*       C  = Wout + (size_t)b * SEQ * SEQ;

    const int tid  = threadIdx.x;
    const int lane = tid & 31, wid = tid >> 5;
    const int wm = wid & 3, wn = wid >> 2;
    const int g  = lane >> 2, tg = lane & 3;

    const int lrow   = tid >> 1;          // 0..127
    const int lchunk = (tid & 1) * 8;     // 0 or 8

    const float* ag = A  + (size_t)lrow * KPAD + lchunk;
    const float* bg = Bm + (size_t)lrow * KPAD + lchunk;

    unsigned a_s[2], b_s[2];
    #pragma unroll
    for (int s = 0; s < 2; ++s) {
        a_s[s] = smem_u32(&As[s][lrow][lchunk]);
        b_s[s] = smem_u32(&Bs[s][lrow][lchunk]);
    }

    float acc[2][8][4];
    #pragma unroll
    for (int mt = 0; mt < 2; ++mt)
        #pragma unroll
        for (int nt = 0; nt < 8; ++nt)
            #pragma unroll
            for (int c = 0; c < 4; ++c) acc[mt][nt][c] = 0.0f;

    const int NIT = KPAD / BK;  // 65
    // prologue: stage 0  (each thread: floats [lchunk, lchunk+8) of its row)
    CP_ASYNC16(a_s[0],      ag);
    CP_ASYNC16(a_s[0] + 16, ag + 4);
    CP_ASYNC16(b_s[0],      bg);
    CP_ASYNC16(b_s[0] + 16, bg + 4);
    CP_COMMIT();

    for (int it = 0; it < NIT; ++it) {
        const int buf = it & 1;
        CP_WAIT0();
        __syncthreads();

        const int nxt = it + 1;
        if (nxt < NIT) {
            const int nb = nxt & 1;
            CP_ASYNC16(a_s[nb],      ag + nxt * BK);
            CP_ASYNC16(a_s[nb] + 16, ag + nxt * BK + 4);
            CP_ASYNC16(b_s[nb],      bg + nxt * BK);
            CP_ASYNC16(b_s[nb] + 16, bg + nxt * BK + 4);
            CP_COMMIT();
        }

        #pragma unroll
        for (int ks = 0; ks < 2; ++ks) {
            const int ko = ks * 8;
            unsigned af[2][4], bf[8][2];
            #pragma unroll
            for (int mt = 0; mt < 2; ++mt) {
                const int r = wm * 32 + mt * 16 + g;
                af[mt][0] = __float_as_uint(As[buf][r    ][ko + tg]);
                af[mt][1] = __float_as_uint(As[buf][r + 8][ko + tg]);
                af[mt][2] = __float_as_uint(As[buf][r    ][ko + tg + 4]);
                af[mt][3] = __float_as_uint(As[buf][r + 8][ko + tg + 4]);
            }
            #pragma unroll
            for (int nt = 0; nt < 8; ++nt) {
                const int c0 = wn * 64 + nt * 8 + g;
                bf[nt][0] = __float_as_uint(Bs[buf][c0][ko + tg]);
                bf[nt][1] = __float_as_uint(Bs[buf][c0][ko + tg + 4]);
            }
            #pragma unroll
            for (int mt = 0; mt < 2; ++mt)
                #pragma unroll
                for (int nt = 0; nt < 8; ++nt)
                    MMA_TF32(acc[mt][nt], af[mt], bf[nt]);
        }
    }

    const float scale = 1.0f / 513.0f;
    #pragma unroll
    for (int mt = 0; mt < 2; ++mt) {
        #pragma unroll
        for (int nt = 0; nt < 8; ++nt) {
            const int row = bM * 128 + wm * 32 + mt * 16 + g;
            const int col = bN * 128 + wn * 64 + nt * 8 + 2 * tg;
            float2 lo = make_float2(acc[mt][nt][0] * scale, acc[mt][nt][1] * scale);
            float2 hi = make_float2(acc[mt][nt][2] * scale, acc[mt][nt][3] * scale);
            *(float2*)(C + (size_t)row * SEQ + col)       = lo;
            *(float2*)(C + (size_t)(row + 8) * SEQ + col) = hi;
        }
    }
}

// ---------------------------------------------------------------------------
// In-place row softmax; writes fp32 weights to d_out and tf32 copy to g_Wt
// ---------------------------------------------------------------------------
__global__ __launch_bounds__(256) void softmax_kernel(float* __restrict__ W)
{
    float* p = W + (size_t)blockIdx.x * SEQ;
    float* q = g_Wt + (size_t)blockIdx.x * SEQ;
    const int t = threadIdx.x;
    __shared__ float red[8];

    float4 v0 = *(float4*)(p + t * 8);
    float4 v1 = *(float4*)(p + t * 8 + 4);
    float v[8] = {v0.x, v0.y, v0.z, v0.w, v1.x, v1.y, v1.z, v1.w};

    float mx = v[0];
    #pragma unroll
    for (int i = 1; i < 8; ++i) mx = fmaxf(mx, v[i]);
    #pragma unroll
    for (int o = 16; o > 0; o >>= 1) mx = fmaxf(mx, __shfl_xor_sync(0xFFFFFFFFu, mx, o));
    if ((t & 31) == 0) red[t >> 5] = mx;
    __syncthreads();
    if (t < 32) {
        float m = (t < 8) ? red[t] : -1e30f;
        #pragma unroll
        for (int o = 4; o > 0; o >>= 1) m = fmaxf(m, __shfl_xor_sync(0xFFFFFFFFu, m, o));
        if (t == 0) red[0] = m;
    }
    __syncthreads();
    mx = red[0];
    __syncthreads();

    float sum = 0.0f;
    #pragma unroll
    for (int i = 0; i < 8; ++i) { v[i] = expf(v[i] - mx); sum += v[i]; }
    #pragma unroll
    for (int o = 16; o > 0; o >>= 1) sum += __shfl_xor_sync(0xFFFFFFFFu, sum, o);
    if ((t & 31) == 0) red[t >> 5] = sum;
    __syncthreads();
    if (t < 32) {
        float s = (t < 8) ? red[t] : 0.0f;
        #pragma unroll
        for (int o = 4; o > 0; o >>= 1) s += __shfl_xor_sync(0xFFFFFFFFu, s, o);
        if (t == 0) red[0] = s;
    }
    __syncthreads();
    const float inv = 1.0f / red[0];

    #pragma unroll
    for (int i = 0; i < 8; ++i) v[i] *= inv;
    v0.x = v[0]; v0.y = v[1]; v0.z = v[2]; v0.w = v[3];
    v1.x = v[4]; v1.y = v[5]; v1.z = v[6]; v1.w = v[7];
    *(float4*)(p + t * 8)     = v0;
    *(float4*)(p + t * 8 + 4) = v1;

    float4 w0, w1;
    w0.x = f2tf32f(v[0]); w0.y = f2tf32f(v[1]); w0.z = f2tf32f(v[2]); w0.w = f2tf32f(v[3]);
    w1.x = f2tf32f(v[4]); w1.y = f2tf32f(v[5]); w1.z = f2tf32f(v[6]); w1.w = f2tf32f(v[7]);
    *(float4*)(q + t * 8)     = w0;
    *(float4*)(q + t * 8 + 4) = w1;
}

// ---------------------------------------------------------------------------
// GEMM 2 (NN, tf32): out = Wt @ Vt  (pre-converted, no in-loop cvt)
// Static smem: As 2*[128][20] + Bs 2*[16][136] = 37,888 B
// ---------------------------------------------------------------------------
__global__ __launch_bounds__(256) void gemm_out_tc(float* __restrict__ O)
{
    __shared__ float As[2][128][APITCH];
    __shared__ float Bs[2][BK][BPITCH];

    const int bN = blockIdx.x, bM = blockIdx.y, b = blockIdx.z;
    const float* A  = g_Wt + (size_t)b * SEQ * SEQ + (size_t)(bM * 128) * SEQ;
    const float* Bv = g_Vt + (size_t)b * SEQ * HID + bN * 128;
    float*       C  = O + (size_t)b * SEQ * HID;

    const int tid  = threadIdx.x;
    const int lane = tid & 31, wid = tid >> 5;
    const int wm = wid & 3, wn = wid >> 2;
    const int g  = lane >> 2, tg = lane & 3;

    const int lrow   = tid >> 1;
    const int lchunk = (tid & 1) * 8;
    const int brow   = tid >> 4;          // 0..15
    const int bcol   = (tid & 15) * 8;    // 0..120

    const float* ag = A  + (size_t)lrow * SEQ + lchunk;
    const float* bg = Bv + (size_t)brow * HID + bcol;

    unsigned a_s[2], b_s[2];
    #pragma unroll
    for (int s = 0; s < 2; ++s) {
        a_s[s] = smem_u32(&As[s][lrow][lchunk]);
        b_s[s] = smem_u32(&Bs[s][brow][bcol]);
    }

    float acc[2][8][4];
    #pragma unroll
    for (int mt = 0; mt < 2; ++mt)
        #pragma unroll
        for (int nt = 0; nt < 8; ++nt)
            #pragma unroll
            for (int c = 0; c < 4; ++c) acc[mt][nt][c] = 0.0f;

    const int NIT = SEQ / BK;  // 128
    CP_ASYNC16(a_s[0],      ag);
    CP_ASYNC16(a_s[0] + 16, ag + 4);
    CP_ASYNC16(b_s[0],      bg);
    CP_ASYNC16(b_s[0] + 16, bg + 4);
    CP_COMMIT();

    for (int it = 0; it < NIT; ++it) {
        const int buf = it & 1;
        CP_WAIT0();
        __syncthreads();

        const int nxt = it + 1;
        if (nxt < NIT) {
            const int nb = nxt & 1;
            CP_ASYNC16(a_s[nb],      ag + nxt * BK);
            CP_ASYNC16(a_s[nb] + 16, ag + nxt * BK + 4);
            CP_ASYNC16(b_s[nb],      bg + (size_t)nxt * BK * HID);
            CP_ASYNC16(b_s[nb] + 16, bg + (size_t)nxt * BK * HID + 4);
            CP_COMMIT();
        }

        #pragma unroll
        for (int ks = 0; ks < 2; ++ks) {
            const int ko = ks * 8;
            unsigned af[2][4], bf[8][2];
            #pragma unroll
            for (int mt = 0; mt < 2; ++mt) {
                const int r = wm * 32 + mt * 16 + g;
                af[mt][0] = __float_as_uint(As[buf][r    ][ko + tg]);
                af[mt][1] = __float_as_uint(As[buf][r + 8][ko + tg]);
                af[mt][2] = __float_as_uint(As[buf][r    ][ko + tg + 4]);
                af[mt][3] = __float_as_uint(As[buf][r + 8][ko + tg + 4]);
            }
            #pragma unroll
            for (int nt = 0; nt < 8; ++nt) {
                const int c0 = wn * 64 + nt * 8 + g;
                bf[nt][0] = __float_as_uint(Bs[buf][ko + tg    ][c0]);
                bf[nt][1] = __float_as_uint(Bs[buf][ko + tg + 4][c0]);
            }
            #pragma unroll
            for (int mt = 0; mt < 2; ++mt)
                #pragma unroll
                for (int nt = 0; nt < 8; ++nt)
                    MMA_TF32(acc[mt][nt], af[mt], bf[nt]);
        }
    }

    #pragma unroll
    for (int mt = 0; mt < 2; ++mt) {
        #pragma unroll
        for (int nt = 0; nt < 8; ++nt) {
            const int row = bM * 128 + wm * 32 + mt * 16 + g;
            const int col = bN * 128 + wn * 64 + nt * 8 + 2 * tg;
            float2 lo = make_float2(acc[mt][nt][0], acc[mt][nt][1]);
            float2 hi = make_float2(acc[mt][nt][2], acc[mt][nt][3]);
            *(float2*)(C + (size_t)row * HID + col)       = lo;
            *(float2*)(C + (size_t)(row + 8) * HID + col) = hi;
        }
    }
}

// ---------------------------------------------------------------------------
// Launch: twiddles + vconv + FFT -> GEMM1 -> softmax -> GEMM2
// Pure kernel launches; no host API calls (graph-capture safe).
// ---------------------------------------------------------------------------
extern "C" void kernel_launch(void* const* d_in, const int* in_sizes, int n_in,
                              void* d_out, int out_size)
{
    const float* Q = (const float*)d_in[0];
    const float* K = (const float*)d_in[1];
    const float* V = (const float*)d_in[2];
    float* out = (float*)d_out;
    float* Wts = out + (size_t)NB * SEQ * HID;

    init_twiddles_kernel<<<1, 256>>>();
    vconv_kernel<<<(NB * SEQ * HID) / (256 * 4), 256>>>(V);
    fft_phase_kernel<<<2 * NROWS, 256>>>(Q, K);

    dim3 g1(SEQ / 128, SEQ / 128, NB);
    gemm_scores_tc<<<g1, 256>>>(Wts);

    softmax_kernel<<<NROWS, 256>>>(Wts);

    dim3 g2(HID / 128, SEQ / 128, NB);
    gemm_out_tc<<<g2, 256>>>(out);
}